// round 4
// baseline (speedup 1.0000x reference)
#include <cuda_runtime.h>
#include <math.h>

// Problem constants
#define TT   2048      // B*L tokens
#define DM   1024
#define LSEQ 1024
#define NHH  16
#define NKV  4
#define HD   64
#define NST  64        // SSM state dim N
#define FF   4096
#define NE   4

// ---------------- scratch (static device globals; no allocations) ----------------
__device__ float g_xn[TT*DM];
__device__ float g_w[TT*4];
__device__ float g_ssm[TT*144];
__device__ float g_y[TT*NHH];      // fused scan output y[t,h]
__device__ float g_gz[TT*DM];
__device__ float g_yg[TT*DM];
__device__ float g_ssd[TT*DM];
__device__ float g_q[TT*DM];
__device__ float g_k[TT*NKV*HD];
__device__ float g_v[TT*NKV*HD];
__device__ float g_attn[TT*DM];
__device__ float g_oattn[TT*DM];
__device__ float g_dws[TT*DM];
__device__ float g_conv[TT*DM];
__device__ float g_x2[TT*DM];
__device__ float g_wfull[TT*4];
__device__ float g_xg[TT*DM];      // gathered expert input
__device__ float g_h1[TT*2*FF];
__device__ float g_hh[TT*FF];
__device__ float g_h2[TT*DM];
__device__ float g_eo[TT*DM];
__device__ int   g_idx[NE*TT];     // per-expert token lists
__device__ int   g_cnt[NE];

// ---------------- helpers ----------------
__device__ __forceinline__ float blockReduceSum(float v){
    __shared__ float red[33];
    int lane = threadIdx.x & 31, wid = threadIdx.x >> 5;
    __syncthreads();
    #pragma unroll
    for (int o = 16; o > 0; o >>= 1) v += __shfl_xor_sync(0xffffffffu, v, o);
    if (lane == 0) red[wid] = v;
    __syncthreads();
    if (wid == 0){
        float s = (lane < (int)(blockDim.x >> 5)) ? red[lane] : 0.f;
        #pragma unroll
        for (int o = 16; o > 0; o >>= 1) s += __shfl_xor_sync(0xffffffffu, s, o);
        if (lane == 0) red[32] = s;
    }
    __syncthreads();
    return red[32];
}

__device__ __forceinline__ float softplusf(float z){
    return (z > 20.f) ? z : log1pf(expf(z));
}
__device__ __forceinline__ float sigmoidf_(float z){
    return 1.f / (1.f + expf(-z));
}

// ---------------- generic SGEMM: C[M,N] = A[M,K] @ B[K,N], all row-major ----------------
// BM=BN=128, BK=8, 256 threads, 8x8 per thread, double-buffered smem staging.
// If cnt != nullptr: blocks with row-base >= *cnt exit early (sparse MoE path).
__global__ __launch_bounds__(256) void sgemm(const float* __restrict__ A,
                                             const float* __restrict__ B,
                                             float* __restrict__ C,
                                             int M, int N, int K,
                                             const int* __restrict__ cnt){
    if (cnt && (int)(blockIdx.y * 128) >= __ldg(cnt)) return;
    __shared__ float As[2][8][128];
    __shared__ float Bs[2][8][128];
    int tid = threadIdx.x;
    int tx = tid & 15, ty = tid >> 4;
    const float* Ab = A + (size_t)blockIdx.y * 128 * K;
    const float* Bb = B + blockIdx.x * 128;
    int arow = tid >> 1, acol = (tid & 1) << 2;     // A tile 128x8
    int brow = tid >> 5, bcol = (tid & 31) << 2;    // B tile 8x128
    const float* Ap = Ab + (size_t)arow * K + acol;
    const float* Bp = Bb + (size_t)brow * N + bcol;

    float acc[8][8];
    #pragma unroll
    for (int i = 0; i < 8; i++)
        #pragma unroll
        for (int j = 0; j < 8; j++) acc[i][j] = 0.f;

    // prologue: stage tile 0 into buffer 0
    {
        float4 av = *(const float4*)Ap;
        float4 bv = *(const float4*)Bp;
        As[0][acol+0][arow] = av.x;
        As[0][acol+1][arow] = av.y;
        As[0][acol+2][arow] = av.z;
        As[0][acol+3][arow] = av.w;
        *(float4*)&Bs[0][brow][bcol] = bv;
    }
    __syncthreads();

    int buf = 0;
    for (int kt = 8; kt <= K; kt += 8){
        float4 av2, bv2;
        bool more = (kt < K);
        if (more){
            av2 = *(const float4*)(Ap + kt);
            bv2 = *(const float4*)(Bp + (size_t)kt * N);
        }
        #pragma unroll
        for (int k = 0; k < 8; k++){
            float a[8], b[8];
            *(float4*)&a[0] = *(const float4*)&As[buf][k][ty*8];
            *(float4*)&a[4] = *(const float4*)&As[buf][k][ty*8+4];
            *(float4*)&b[0] = *(const float4*)&Bs[buf][k][tx*8];
            *(float4*)&b[4] = *(const float4*)&Bs[buf][k][tx*8+4];
            #pragma unroll
            for (int i = 0; i < 8; i++)
                #pragma unroll
                for (int j = 0; j < 8; j++)
                    acc[i][j] += a[i]*b[j];
        }
        if (more){
            int nb = buf ^ 1;
            As[nb][acol+0][arow] = av2.x;
            As[nb][acol+1][arow] = av2.y;
            As[nb][acol+2][arow] = av2.z;
            As[nb][acol+3][arow] = av2.w;
            *(float4*)&Bs[nb][brow][bcol] = bv2;
            __syncthreads();
            buf = nb;
        }
    }
    float* Cb = C + (size_t)(blockIdx.y*128 + ty*8) * N + blockIdx.x*128 + tx*8;
    #pragma unroll
    for (int i = 0; i < 8; i++){
        *(float4*)&Cb[(size_t)i*N]   = make_float4(acc[i][0], acc[i][1], acc[i][2], acc[i][3]);
        *(float4*)&Cb[(size_t)i*N+4] = make_float4(acc[i][4], acc[i][5], acc[i][6], acc[i][7]);
    }
}

// ---------------- K1: xn = rms(x)*n1w + goal; router weights w; ssm = xn @ xproj ----------------
__global__ __launch_bounds__(256) void k_pre(const float* __restrict__ x,
                                             const float* __restrict__ goal,
                                             const float* __restrict__ n1w,
                                             const float* __restrict__ rw,
                                             const float* __restrict__ xw){
    int t = blockIdx.x, tid = threadIdx.x;
    __shared__ float sx[DM];
    __shared__ float r4[4];
    const float4* x4 = (const float4*)(x + (size_t)t*DM);
    float4 xv = x4[tid];
    float ss = xv.x*xv.x + xv.y*xv.y + xv.z*xv.z + xv.w*xv.w;
    ss = blockReduceSum(ss);
    float rs = rsqrtf(ss / (float)DM + 1e-6f);
    float4 gv = ((const float4*)(goal + (size_t)t*DM))[tid];
    float4 wv = ((const float4*)n1w)[tid];
    float4 o;
    o.x = xv.x*rs*wv.x + gv.x;
    o.y = xv.y*rs*wv.y + gv.y;
    o.z = xv.z*rs*wv.z + gv.z;
    o.w = xv.w*rs*wv.w + gv.w;
    ((float4*)(g_xn + (size_t)t*DM))[tid] = o;
    ((float4*)sx)[tid] = o;
    __syncthreads();

    float acc = 0.f;
    if (tid < 148){
        const float* wp; int stride;
        if (tid < 4){ wp = rw + tid; stride = 4; }
        else        { wp = xw + (tid - 4); stride = 144; }
        #pragma unroll 4
        for (int k = 0; k < DM; k++) acc += sx[k] * wp[(size_t)k*stride];
    }
    if (tid < 4) r4[tid] = acc;
    else if (tid < 148) g_ssm[(size_t)t*144 + (tid-4)] = acc;
    __syncthreads();
    if (tid == 0){
        const float mix[4] = {0.5f, 0.2f, 0.15f, 0.15f};
        float m = r4[0];
        for (int e = 1; e < 4; e++) m = fmaxf(m, r4[e]);
        float e4[4], s = 0.f;
        for (int e = 0; e < 4; e++){ e4[e] = expf(r4[e]-m); s += e4[e]; }
        float ws = 0.f, wv2[4];
        for (int e = 0; e < 4; e++){ wv2[e] = e4[e]/s*mix[e]; ws += wv2[e]; }
        for (int e = 0; e < 4; e++) g_w[t*4+e] = wv2[e]/ws;
    }
}

// ---------------- K2: fused SSM scan + C-contraction. 1 warp per (b,h). ----------------
// y[t,h] = sum_n states[t,h,n] * Cs[t,n], states never materialized.
__global__ void k_scan(const float* __restrict__ Amat){
    int bh = blockIdx.x;            // 0..31
    int b = bh >> 4, h = bh & 15;
    int lane = threadIdx.x;         // 32 threads
    float a1 = Amat[h*NST + lane];
    float a2 = Amat[h*NST + lane + 32];
    float s1 = 0.f, s2 = 0.f;
    int base = b * LSEQ;
    for (int t = 0; t < LSEQ; t++){
        const float* row = g_ssm + (size_t)(base + t) * 144;
        float db = row[128 + h];
        float z1 = db + row[lane];
        float z2 = db + row[lane + 32];
        float dt1 = softplusf(z1);
        float dt2 = softplusf(z2);
        s1 = expf(dt1 * a1) * s1 + dt1 * dt1;
        s2 = expf(dt2 * a2) * s2 + dt2 * dt2;
        float p = s1 * row[64 + lane] + s2 * row[64 + lane + 32];
        #pragma unroll
        for (int o = 16; o > 0; o >>= 1) p += __shfl_xor_sync(0xffffffffu, p, o);
        if (lane == 0) g_y[(base + t)*NHH + h] = p;
    }
}

// ---------------- K3: yg = (y + xn*Dp) * sigmoid(gz + gate_b) ----------------
__global__ __launch_bounds__(256) void k_yg(const float* __restrict__ gate_b,
                                            const float* __restrict__ Dp){
    int t = blockIdx.x, tid = threadIdx.x;
    __shared__ float ys[NHH];
    if (tid < NHH) ys[tid] = g_y[t*NHH + tid];
    __syncthreads();
    size_t base = (size_t)t*DM;
    #pragma unroll
    for (int i = 0; i < 4; i++){
        int d = tid + (i << 8);
        int h = d >> 6;
        float gate = sigmoidf_(g_gz[base+d] + gate_b[d]);
        float yv = ys[h] + g_xn[base+d]*Dp[h];
        g_yg[base+d] = yv * gate;
    }
}

// ---------------- K4: per-head RMS + RoPE, in place. 1 warp per (token, head) ----------------
__global__ void k_rope(float* __restrict__ buf, const float* __restrict__ w, int nh){
    int gw = blockIdx.x * (blockDim.x >> 5) + (threadIdx.x >> 5);
    int lane = threadIdx.x & 31;
    int t = gw / nh, head = gw % nh;
    int pos = t & (LSEQ - 1);
    float* p = buf + ((size_t)t*nh + head)*HD;
    float u1 = p[lane], u2 = p[lane + 32];
    float ss = u1*u1 + u2*u2;
    #pragma unroll
    for (int o = 16; o > 0; o >>= 1) ss += __shfl_xor_sync(0xffffffffu, ss, o);
    float rs = rsqrtf(ss / 64.f + 1e-6f);
    u1 *= rs * w[lane];
    u2 *= rs * w[lane + 32];
    float ang = (float)pos * powf(10000.f, -(float)lane / 32.f);
    float c = cosf(ang), sn = sinf(ang);
    p[lane]      = u1*c - u2*sn;
    p[lane + 32] = u2*c + u1*sn;
}

// ---------------- K5: flash attention. grid (L/64, H, B), 256 threads ----------------
__global__ __launch_bounds__(256) void k_attn(){
    __shared__ float sQ[4096];   // 64x64
    __shared__ float sKP[4096];  // K tile, then reused as P tile
    __shared__ float sV[4096];
    int qt = blockIdx.x, h = blockIdx.y, b = blockIdx.z;
    int kvh = h >> 2;
    int tid = threadIdx.x;
    int r = tid >> 2, c4 = tid & 3;
    int q0 = qt * 64;

    for (int i = tid; i < 1024; i += 256){
        int row = i >> 4, cc = (i & 15) << 2;
        *(float4*)&sQ[row*64 + cc] =
            *(const float4*)&g_q[(((size_t)(b*LSEQ + q0 + row))*NHH + h)*HD + cc];
    }

    float m = -1e30f, lsum = 0.f;
    float acc[16];
    #pragma unroll
    for (int j = 0; j < 16; j++) acc[j] = 0.f;

    for (int kt = 0; kt < 16; kt++){
        __syncthreads();
        for (int i = tid; i < 1024; i += 256){
            int row = i >> 4, cc = (i & 15) << 2;
            size_t gk = (((size_t)(b*LSEQ + kt*64 + row))*NKV + kvh)*HD + cc;
            *(float4*)&sKP[row*64 + cc] = *(const float4*)&g_k[gk];
            *(float4*)&sV[row*64 + cc]  = *(const float4*)&g_v[gk];
        }
        __syncthreads();
        float s[16];
        #pragma unroll
        for (int j = 0; j < 16; j++){
            int c = c4*16 + j;
            float a2 = 0.f;
            #pragma unroll
            for (int kk = 0; kk < 64; kk += 4){
                float4 qa = *(const float4*)&sQ[r*64 + kk];
                float4 ka = *(const float4*)&sKP[c*64 + kk];
                a2 += qa.x*ka.x + qa.y*ka.y + qa.z*ka.z + qa.w*ka.w;
            }
            s[j] = a2 * 0.125f;
        }
        float tm = s[0];
        #pragma unroll
        for (int j = 1; j < 16; j++) tm = fmaxf(tm, s[j]);
        tm = fmaxf(tm, __shfl_xor_sync(0xffffffffu, tm, 1, 4));
        tm = fmaxf(tm, __shfl_xor_sync(0xffffffffu, tm, 2, 4));
        float nm = fmaxf(m, tm);
        float alpha = expf(m - nm);
        float ps = 0.f;
        #pragma unroll
        for (int j = 0; j < 16; j++){ s[j] = expf(s[j] - nm); ps += s[j]; }
        ps += __shfl_xor_sync(0xffffffffu, ps, 1, 4);
        ps += __shfl_xor_sync(0xffffffffu, ps, 2, 4);
        lsum = lsum*alpha + ps;
        m = nm;
        #pragma unroll
        for (int j = 0; j < 16; j++) acc[j] *= alpha;
        __syncthreads();                 // everyone done reading K from sKP
        #pragma unroll
        for (int j = 0; j < 16; j++) sKP[r*64 + c4*16 + j] = s[j];
        __syncthreads();
        for (int jj = 0; jj < 64; jj++){
            float p = sKP[r*64 + jj];
            const float* vrow = &sV[jj*64 + c4*16];
            #pragma unroll
            for (int dd = 0; dd < 16; dd += 4){
                float4 vv = *(const float4*)&vrow[dd];
                acc[dd]   += p*vv.x;
                acc[dd+1] += p*vv.y;
                acc[dd+2] += p*vv.z;
                acc[dd+3] += p*vv.w;
            }
        }
    }
    float inv = 1.f / lsum;
    size_t ob = ((size_t)(b*LSEQ + q0 + r)*NHH + h)*HD + c4*16;
    #pragma unroll
    for (int dd = 0; dd < 16; dd += 4){
        *(float4*)&g_attn[ob + dd] =
            make_float4(acc[dd]*inv, acc[dd+1]*inv, acc[dd+2]*inv, acc[dd+3]*inv);
    }
}

// ---------------- K6: conv branch dw + silu ----------------
__global__ void k_conv(const float* __restrict__ dw_w, const float* __restrict__ dw_b){
    int idx = blockIdx.x*blockDim.x + threadIdx.x;
    int t = idx >> 10, d = idx & 1023;
    int lp = t & (LSEQ - 1);
    float c = dw_b[d] + g_xn[idx]*dw_w[d*3 + 1];
    if (lp > 0)        c += g_xn[idx - DM]*dw_w[d*3 + 0];
    if (lp < LSEQ - 1) c += g_xn[idx + DM]*dw_w[d*3 + 2];
    g_dws[idx] = c * sigmoidf_(c);
}

// ---------------- K7: mix branches, write x2 (and to out) ----------------
__global__ void k_mix(const float* __restrict__ x, const float* __restrict__ mem,
                      const float* __restrict__ pw_b, float* __restrict__ out){
    int idx = blockIdx.x*blockDim.x + threadIdx.x;
    int t = idx >> 10, d = idx & 1023;
    const float* wt = g_w + t*4;
    float v = x[idx] + wt[0]*g_ssd[idx] + wt[1]*g_oattn[idx]
            + wt[2]*(g_conv[idx] + pw_b[d]) + wt[3]*mem[idx];
    g_x2[idx] = v;
    out[idx] = v;
}

// ---------------- K8a: reset per-expert counters ----------------
__global__ void k_reset(){
    if (threadIdx.x < NE) g_cnt[threadIdx.x] = 0;
}

// ---------------- K8: MoE gating: rms(x2)@moe_gate -> softmax -> top2; build token lists ----------------
__global__ __launch_bounds__(256) void k_moegate(const float* __restrict__ n2w,
                                                 const float* __restrict__ mg){
    int t = blockIdx.x, tid = threadIdx.x;
    float4 xv = ((const float4*)(g_x2 + (size_t)t*DM))[tid];
    float ss = xv.x*xv.x + xv.y*xv.y + xv.z*xv.z + xv.w*xv.w;
    ss = blockReduceSum(ss);
    float rs = rsqrtf(ss / (float)DM + 1e-6f);
    float4 wv = ((const float4*)n2w)[tid];
    float v0 = xv.x*rs*wv.x, v1 = xv.y*rs*wv.y, v2 = xv.z*rs*wv.z, v3 = xv.w*rs*wv.w;
    int kb = tid*4;
    const float4* mg4 = (const float4*)mg;   // row k of (1024,4) is one float4
    float4 m0 = mg4[kb], m1 = mg4[kb+1], m2 = mg4[kb+2], m3 = mg4[kb+3];
    float a0 = v0*m0.x + v1*m1.x + v2*m2.x + v3*m3.x;
    float a1 = v0*m0.y + v1*m1.y + v2*m2.y + v3*m3.y;
    float a2 = v0*m0.z + v1*m1.z + v2*m2.z + v3*m3.z;
    float a3 = v0*m0.w + v1*m1.w + v2*m2.w + v3*m3.w;
    a0 = blockReduceSum(a0);
    a1 = blockReduceSum(a1);
    a2 = blockReduceSum(a2);
    a3 = blockReduceSum(a3);
    if (tid == 0){
        float l[4] = {a0, a1, a2, a3};
        float mx = fmaxf(fmaxf(l[0], l[1]), fmaxf(l[2], l[3]));
        float e4[4], s = 0.f;
        for (int e = 0; e < 4; e++){ e4[e] = expf(l[e]-mx); s += e4[e]; }
        float gp[4];
        for (int e = 0; e < 4; e++) gp[e] = e4[e]/s;
        int i1 = 0;
        for (int e = 1; e < 4; e++) if (gp[e] > gp[i1]) i1 = e;
        int i2 = -1;
        for (int e = 0; e < 4; e++){
            if (e == i1) continue;
            if (i2 < 0 || gp[e] > gp[i2]) i2 = e;
        }
        float wf[4] = {0.f, 0.f, 0.f, 0.f};
        wf[i1] = gp[i1]; wf[i2] = gp[i2];
        for (int e = 0; e < 4; e++) g_wfull[t*4+e] = wf[e];
        int p1 = atomicAdd(&g_cnt[i1], 1);
        g_idx[i1*TT + p1] = t;
        int p2 = atomicAdd(&g_cnt[i2], 1);
        g_idx[i2*TT + p2] = t;
    }
}

// ---------------- K8b: gather assigned tokens into g_xg for expert e ----------------
__global__ __launch_bounds__(256) void k_gather(int e){
    int i = blockIdx.x;                 // gathered row
    if (i >= g_cnt[e]) return;
    int t = g_idx[e*TT + i];
    ((float4*)(g_xg + (size_t)i*DM))[threadIdx.x] =
        ((const float4*)(g_x2 + (size_t)t*DM))[threadIdx.x];
}

// ---------------- K9: MoE activation: hh = silu(a)*g (guarded by cnt) ----------------
__global__ void k_act(int e){
    int idx = blockIdx.x*blockDim.x + threadIdx.x;
    int t = idx >> 12, f = idx & 4095;
    if (t >= g_cnt[e]) return;
    float a = g_h1[(size_t)t*2*FF + f];
    float g = g_h1[(size_t)t*2*FF + FF + f];
    g_hh[idx] = a * sigmoidf_(a) * g;
}

// ---------------- K10: scatter expert output back into out ----------------
__global__ __launch_bounds__(256) void k_scatter(float* __restrict__ out,
                                                 const float* __restrict__ bias, int e){
    int i = blockIdx.x;
    if (i >= g_cnt[e]) return;
    int t = g_idx[e*TT + i];
    float w = g_wfull[t*4 + e];
    int tid = threadIdx.x;
    float4 eo = ((const float4*)(g_eo + (size_t)i*DM))[tid];
    float4 bv = ((const float4*)bias)[tid];
    float4 ov = ((float4*)(out + (size_t)t*DM))[tid];
    ov.x += w * (eo.x + bv.x);
    ov.y += w * (eo.y + bv.y);
    ov.z += w * (eo.z + bv.z);
    ov.w += w * (eo.w + bv.w);
    ((float4*)(out + (size_t)t*DM))[tid] = ov;
}

// ---------------- host ----------------
extern "C" void kernel_launch(void* const* d_in, const int* in_sizes, int n_in,
                              void* d_out, int out_size) {
    const float* x      = (const float*)d_in[0];
    const float* goal   = (const float*)d_in[1];
    const float* mem    = (const float*)d_in[2];
    const float* n1w    = (const float*)d_in[3];
    const float* n2w    = (const float*)d_in[4];
    const float* rw     = (const float*)d_in[5];
    const float* xw     = (const float*)d_in[6];
    const float* Amat   = (const float*)d_in[7];
    const float* Dp     = (const float*)d_in[8];
    const float* gate_w = (const float*)d_in[9];
    const float* gate_b = (const float*)d_in[10];
    const float* ssd_o  = (const float*)d_in[11];
    const float* q_w    = (const float*)d_in[12];
    const float* k_w    = (const float*)d_in[13];
    const float* v_w    = (const float*)d_in[14];
    const float* o_w    = (const float*)d_in[15];
    const float* qn     = (const float*)d_in[16];
    const float* kn     = (const float*)d_in[17];
    const float* dw_w   = (const float*)d_in[18];
    const float* dw_b   = (const float*)d_in[19];
    const float* pw_w   = (const float*)d_in[20];
    const float* pw_b   = (const float*)d_in[21];
    const float* mg     = (const float*)d_in[22];
    const float* ew1    = (const float*)d_in[23];
    const float* ew2    = (const float*)d_in[24];
    const float* elw    = (const float*)d_in[25];
    const float* elb    = (const float*)d_in[26];
    float* out = (float*)d_out;

    float *p_xn, *p_gz, *p_yg, *p_ssd, *p_q, *p_k, *p_v, *p_attn, *p_oattn,
          *p_dws, *p_conv, *p_x2, *p_xg, *p_h1, *p_hh, *p_h2, *p_eo;
    int *p_cnt;
    cudaGetSymbolAddress((void**)&p_xn,   g_xn);
    cudaGetSymbolAddress((void**)&p_gz,   g_gz);
    cudaGetSymbolAddress((void**)&p_yg,   g_yg);
    cudaGetSymbolAddress((void**)&p_ssd,  g_ssd);
    cudaGetSymbolAddress((void**)&p_q,    g_q);
    cudaGetSymbolAddress((void**)&p_k,    g_k);
    cudaGetSymbolAddress((void**)&p_v,    g_v);
    cudaGetSymbolAddress((void**)&p_attn, g_attn);
    cudaGetSymbolAddress((void**)&p_oattn,g_oattn);
    cudaGetSymbolAddress((void**)&p_dws,  g_dws);
    cudaGetSymbolAddress((void**)&p_conv, g_conv);
    cudaGetSymbolAddress((void**)&p_x2,   g_x2);
    cudaGetSymbolAddress((void**)&p_xg,   g_xg);
    cudaGetSymbolAddress((void**)&p_h1,   g_h1);
    cudaGetSymbolAddress((void**)&p_hh,   g_hh);
    cudaGetSymbolAddress((void**)&p_h2,   g_h2);
    cudaGetSymbolAddress((void**)&p_eo,   g_eo);
    cudaGetSymbolAddress((void**)&p_cnt,  g_cnt);

    // 1. pre: xn, router weights, ssm projection
    k_pre<<<TT, 256>>>(x, goal, n1w, rw, xw);
    // 2. fused SSM scan + C contraction
    k_scan<<<NHH*2, 32>>>(Amat);
    // 3. gate projection + yg
    sgemm<<<dim3(DM/128, TT/128), 256>>>(p_xn, gate_w, p_gz, TT, DM, DM, nullptr);
    k_yg<<<TT, 256>>>(gate_b, Dp);
    // 4. ssd output projection
    sgemm<<<dim3(DM/128, TT/128), 256>>>(p_yg, ssd_o, p_ssd, TT, DM, DM, nullptr);
    // 5. attention: q/k/v projections, rms+rope, flash attn, out proj
    sgemm<<<dim3(DM/128, TT/128), 256>>>(p_xn, q_w, p_q, TT, DM, DM, nullptr);
    sgemm<<<dim3(2, TT/128), 256>>>(p_xn, k_w, p_k, TT, NKV*HD, DM, nullptr);
    sgemm<<<dim3(2, TT/128), 256>>>(p_xn, v_w, p_v, TT, NKV*HD, DM, nullptr);
    k_rope<<<TT*NHH/4, 128>>>(p_q, qn, NHH);
    k_rope<<<TT*NKV/4, 128>>>(p_k, kn, NKV);
    k_attn<<<dim3(LSEQ/64, NHH, 2), 256>>>();
    sgemm<<<dim3(DM/128, TT/128), 256>>>(p_attn, o_w, p_oattn, TT, DM, DM, nullptr);
    // 6. conv branch
    k_conv<<<TT*DM/256, 256>>>(dw_w, dw_b);
    sgemm<<<dim3(DM/128, TT/128), 256>>>(p_dws, pw_w, p_conv, TT, DM, DM, nullptr);
    // 7. mix -> x2 (also seeds out)
    k_mix<<<TT*DM/256, 256>>>(x, mem, pw_b, out);
    // 8. MoE gating + token lists
    k_reset<<<1, 32>>>();
    k_moegate<<<TT, 256>>>(n2w, mg);
    // 9. MoE experts — top-2 sparse: only assigned tokens computed (exact, since
    //    non-selected expert weights are identically zero in the reference).
    for (int e = 0; e < 4; e++){
        k_gather<<<TT, 256>>>(e);
        sgemm<<<dim3(2*FF/128, TT/128), 256>>>(p_xg, ew1 + (size_t)e*DM*2*FF, p_h1, TT, 2*FF, DM, p_cnt);
        k_act<<<TT*FF/256, 256>>>(e);
        sgemm<<<dim3(DM/128, TT/128), 256>>>(p_hh, ew2 + (size_t)e*FF*DM, p_h2, TT, DM, FF, p_cnt);
        sgemm<<<dim3(DM/128, TT/128), 256>>>(p_h2, elw + (size_t)e*DM*DM, p_eo, TT, DM, DM, p_cnt);
        k_scatter<<<TT, 256>>>(out, elb + (size_t)e*DM, e);
    }
}

// round 5
// speedup vs baseline: 1.5885x; 1.5885x over previous
#include <cuda_runtime.h>
#include <math.h>

// Problem constants
#define TT   2048      // B*L tokens
#define DM   1024
#define LSEQ 1024
#define NHH  16
#define NKV  4
#define HD   64
#define NST  64        // SSM state dim N
#define FF   4096
#define NE   4

// ---------------- scratch (static device globals; no allocations) ----------------
__device__ float g_xn[TT*DM];
__device__ float g_w[TT*4];
__device__ float g_ssm[TT*144];
__device__ float g_y[TT*NHH];      // fused scan output y[t,h]
__device__ float g_gz[TT*DM];
__device__ float g_yg[TT*DM];
__device__ float g_ssd[TT*DM];
__device__ float g_q[TT*DM];
__device__ float g_k[TT*NKV*HD];
__device__ float g_v[TT*NKV*HD];
__device__ float g_attn[TT*DM];
__device__ float g_oattn[TT*DM];
__device__ float g_dws[TT*DM];
__device__ float g_conv[TT*DM];
__device__ float g_x2[TT*DM];
__device__ float g_wfull[TT*4];
__device__ float g_xg[TT*DM];      // gathered expert input
__device__ float g_h1[TT*2*FF];
__device__ float g_hh[TT*FF];
__device__ float g_h2[TT*DM];
__device__ float g_eo[TT*DM];
__device__ int   g_idx[NE*TT];     // per-expert token lists
__device__ int   g_cnt[NE];

// ---------------- helpers ----------------
__device__ __forceinline__ float blockReduceSum(float v){
    __shared__ float red[33];
    int lane = threadIdx.x & 31, wid = threadIdx.x >> 5;
    __syncthreads();
    #pragma unroll
    for (int o = 16; o > 0; o >>= 1) v += __shfl_xor_sync(0xffffffffu, v, o);
    if (lane == 0) red[wid] = v;
    __syncthreads();
    if (wid == 0){
        float s = (lane < (int)(blockDim.x >> 5)) ? red[lane] : 0.f;
        #pragma unroll
        for (int o = 16; o > 0; o >>= 1) s += __shfl_xor_sync(0xffffffffu, s, o);
        if (lane == 0) red[32] = s;
    }
    __syncthreads();
    return red[32];
}

__device__ __forceinline__ float softplusf(float z){
    return (z > 20.f) ? z : log1pf(expf(z));
}
__device__ __forceinline__ float sigmoidf_(float z){
    return 1.f / (1.f + expf(-z));
}
__device__ __forceinline__ unsigned f2tf(float x){
    unsigned r; asm("cvt.rna.tf32.f32 %0, %1;" : "=r"(r) : "f"(x)); return r;
}

// ---------------- generic SGEMM (fp32 SIMT): C[M,N] = A[M,K] @ B[K,N] ----------------
// BM=BN=128, BK=8, 256 threads, 8x8 per thread, double-buffered smem staging.
__global__ __launch_bounds__(256) void sgemm(const float* __restrict__ A,
                                             const float* __restrict__ B,
                                             float* __restrict__ C,
                                             int M, int N, int K,
                                             const int* __restrict__ cnt){
    if (cnt && (int)(blockIdx.y * 128) >= __ldg(cnt)) return;
    __shared__ float As[2][8][128];
    __shared__ float Bs[2][8][128];
    int tid = threadIdx.x;
    int tx = tid & 15, ty = tid >> 4;
    const float* Ab = A + (size_t)blockIdx.y * 128 * K;
    const float* Bb = B + blockIdx.x * 128;
    int arow = tid >> 1, acol = (tid & 1) << 2;     // A tile 128x8
    int brow = tid >> 5, bcol = (tid & 31) << 2;    // B tile 8x128
    const float* Ap = Ab + (size_t)arow * K + acol;
    const float* Bp = Bb + (size_t)brow * N + bcol;

    float acc[8][8];
    #pragma unroll
    for (int i = 0; i < 8; i++)
        #pragma unroll
        for (int j = 0; j < 8; j++) acc[i][j] = 0.f;

    {
        float4 av = *(const float4*)Ap;
        float4 bv = *(const float4*)Bp;
        As[0][acol+0][arow] = av.x;
        As[0][acol+1][arow] = av.y;
        As[0][acol+2][arow] = av.z;
        As[0][acol+3][arow] = av.w;
        *(float4*)&Bs[0][brow][bcol] = bv;
    }
    __syncthreads();

    int buf = 0;
    for (int kt = 8; kt <= K; kt += 8){
        float4 av2, bv2;
        bool more = (kt < K);
        if (more){
            av2 = *(const float4*)(Ap + kt);
            bv2 = *(const float4*)(Bp + (size_t)kt * N);
        }
        #pragma unroll
        for (int k = 0; k < 8; k++){
            float a[8], b[8];
            *(float4*)&a[0] = *(const float4*)&As[buf][k][ty*8];
            *(float4*)&a[4] = *(const float4*)&As[buf][k][ty*8+4];
            *(float4*)&b[0] = *(const float4*)&Bs[buf][k][tx*8];
            *(float4*)&b[4] = *(const float4*)&Bs[buf][k][tx*8+4];
            #pragma unroll
            for (int i = 0; i < 8; i++)
                #pragma unroll
                for (int j = 0; j < 8; j++)
                    acc[i][j] += a[i]*b[j];
        }
        if (more){
            int nb = buf ^ 1;
            As[nb][acol+0][arow] = av2.x;
            As[nb][acol+1][arow] = av2.y;
            As[nb][acol+2][arow] = av2.z;
            As[nb][acol+3][arow] = av2.w;
            *(float4*)&Bs[nb][brow][bcol] = bv2;
            __syncthreads();
            buf = nb;
        }
    }
    float* Cb = C + (size_t)(blockIdx.y*128 + ty*8) * N + blockIdx.x*128 + tx*8;
    #pragma unroll
    for (int i = 0; i < 8; i++){
        *(float4*)&Cb[(size_t)i*N]   = make_float4(acc[i][0], acc[i][1], acc[i][2], acc[i][3]);
        *(float4*)&Cb[(size_t)i*N+4] = make_float4(acc[i][4], acc[i][5], acc[i][6], acc[i][7]);
    }
}

// ---------------- TF32 tensor-core GEMM: C[M,N] = A[M,K] @ B[K,N] ----------------
// BM=BN=128, BK=16, 256 threads (8 warps, 2x4), warp tile 64x32, m16n8k8 mma.
// Used ONLY for MoE expert GEMMs (no routing decisions downstream of C).
__global__ __launch_bounds__(256) void gemm_tf32(const float* __restrict__ A,
                                                 const float* __restrict__ B,
                                                 float* __restrict__ C,
                                                 int M, int N, int K,
                                                 const int* __restrict__ cnt){
    if (cnt && (int)(blockIdx.y * 128) >= __ldg(cnt)) return;
    __shared__ unsigned As[2][128][20];   // [m][k], pitch 20 -> conflict-free frag loads
    __shared__ unsigned Bs[2][16][136];   // [k][n], pitch 136 -> conflict-free frag loads
    int tid = threadIdx.x;
    int lane = tid & 31, warp = tid >> 5;
    int wm = (warp & 1) << 6;             // warp m-offset: 0/64
    int wn = (warp >> 1) << 5;            // warp n-offset: 0/32/64/96
    int q = lane >> 2, r = lane & 3;

    const float* Ab = A + (size_t)blockIdx.y * 128 * K;
    const float* Bb = B + (size_t)blockIdx.x * 128;

    // staging: A tile 128x16 = 512 float4 (2/thread); B tile 16x128 = 512 float4 (2/thread)
    int arow0 = tid >> 2,        acol = (tid & 3) << 2;
    int arow1 = arow0 + 64;
    int brow0 = tid >> 5,        bcol = (tid & 31) << 2;
    int brow1 = brow0 + 8;

    float c[16][4];
    #pragma unroll
    for (int i = 0; i < 16; i++)
        #pragma unroll
        for (int j = 0; j < 4; j++) c[i][j] = 0.f;

    // prologue: stage tile 0
    {
        float4 av0 = *(const float4*)(Ab + (size_t)arow0*K + acol);
        float4 av1 = *(const float4*)(Ab + (size_t)arow1*K + acol);
        float4 bv0 = *(const float4*)(Bb + (size_t)brow0*N + bcol);
        float4 bv1 = *(const float4*)(Bb + (size_t)brow1*N + bcol);
        As[0][arow0][acol+0]=f2tf(av0.x); As[0][arow0][acol+1]=f2tf(av0.y);
        As[0][arow0][acol+2]=f2tf(av0.z); As[0][arow0][acol+3]=f2tf(av0.w);
        As[0][arow1][acol+0]=f2tf(av1.x); As[0][arow1][acol+1]=f2tf(av1.y);
        As[0][arow1][acol+2]=f2tf(av1.z); As[0][arow1][acol+3]=f2tf(av1.w);
        Bs[0][brow0][bcol+0]=f2tf(bv0.x); Bs[0][brow0][bcol+1]=f2tf(bv0.y);
        Bs[0][brow0][bcol+2]=f2tf(bv0.z); Bs[0][brow0][bcol+3]=f2tf(bv0.w);
        Bs[0][brow1][bcol+0]=f2tf(bv1.x); Bs[0][brow1][bcol+1]=f2tf(bv1.y);
        Bs[0][brow1][bcol+2]=f2tf(bv1.z); Bs[0][brow1][bcol+3]=f2tf(bv1.w);
    }
    __syncthreads();

    int buf = 0;
    for (int kt = 16; kt <= K; kt += 16){
        float4 av0, av1, bv0, bv1;
        bool more = (kt < K);
        if (more){
            av0 = *(const float4*)(Ab + (size_t)arow0*K + kt + acol);
            av1 = *(const float4*)(Ab + (size_t)arow1*K + kt + acol);
            bv0 = *(const float4*)(Bb + (size_t)(brow0 + kt)*N + bcol);
            bv1 = *(const float4*)(Bb + (size_t)(brow1 + kt)*N + bcol);
        }
        #pragma unroll
        for (int ks = 0; ks < 16; ks += 8){
            unsigned af[4][4], bf[4][2];
            #pragma unroll
            for (int mf = 0; mf < 4; mf++){
                int m0 = wm + mf*16;
                af[mf][0] = As[buf][m0 + q    ][ks + r    ];
                af[mf][1] = As[buf][m0 + q + 8][ks + r    ];
                af[mf][2] = As[buf][m0 + q    ][ks + r + 4];
                af[mf][3] = As[buf][m0 + q + 8][ks + r + 4];
            }
            #pragma unroll
            for (int nf = 0; nf < 4; nf++){
                int n0 = wn + nf*8;
                bf[nf][0] = Bs[buf][ks + r    ][n0 + q];
                bf[nf][1] = Bs[buf][ks + r + 4][n0 + q];
            }
            #pragma unroll
            for (int mf = 0; mf < 4; mf++)
                #pragma unroll
                for (int nf = 0; nf < 4; nf++){
                    float* cc = c[mf*4 + nf];
                    asm volatile(
                        "mma.sync.aligned.m16n8k8.row.col.f32.tf32.tf32.f32 "
                        "{%0,%1,%2,%3}, {%4,%5,%6,%7}, {%8,%9}, {%0,%1,%2,%3};"
                        : "+f"(cc[0]), "+f"(cc[1]), "+f"(cc[2]), "+f"(cc[3])
                        : "r"(af[mf][0]), "r"(af[mf][1]), "r"(af[mf][2]), "r"(af[mf][3]),
                          "r"(bf[nf][0]), "r"(bf[nf][1]));
                }
        }
        if (more){
            int nb = buf ^ 1;
            As[nb][arow0][acol+0]=f2tf(av0.x); As[nb][arow0][acol+1]=f2tf(av0.y);
            As[nb][arow0][acol+2]=f2tf(av0.z); As[nb][arow0][acol+3]=f2tf(av0.w);
            As[nb][arow1][acol+0]=f2tf(av1.x); As[nb][arow1][acol+1]=f2tf(av1.y);
            As[nb][arow1][acol+2]=f2tf(av1.z); As[nb][arow1][acol+3]=f2tf(av1.w);
            Bs[nb][brow0][bcol+0]=f2tf(bv0.x); Bs[nb][brow0][bcol+1]=f2tf(bv0.y);
            Bs[nb][brow0][bcol+2]=f2tf(bv0.z); Bs[nb][brow0][bcol+3]=f2tf(bv0.w);
            Bs[nb][brow1][bcol+0]=f2tf(bv1.x); Bs[nb][brow1][bcol+1]=f2tf(bv1.y);
            Bs[nb][brow1][bcol+2]=f2tf(bv1.z); Bs[nb][brow1][bcol+3]=f2tf(bv1.w);
            __syncthreads();
            buf = nb;
        }
    }
    // epilogue: c layout — row0 = q, row1 = q+8, cols (r*2, r*2+1)
    int rowbase = blockIdx.y*128 + wm + q;
    int colbase = blockIdx.x*128 + wn + (r << 1);
    #pragma unroll
    for (int mf = 0; mf < 4; mf++){
        #pragma unroll
        for (int nf = 0; nf < 4; nf++){
            float* cc = c[mf*4 + nf];
            int row0 = rowbase + mf*16;
            int col  = colbase + nf*8;
            *(float2*)&C[(size_t)row0*N + col]      = make_float2(cc[0], cc[1]);
            *(float2*)&C[(size_t)(row0+8)*N + col]  = make_float2(cc[2], cc[3]);
        }
    }
}

// ---------------- K1: xn = rms(x)*n1w + goal; router weights w; ssm = xn @ xproj ----------------
__global__ __launch_bounds__(256) void k_pre(const float* __restrict__ x,
                                             const float* __restrict__ goal,
                                             const float* __restrict__ n1w,
                                             const float* __restrict__ rw,
                                             const float* __restrict__ xw){
    int t = blockIdx.x, tid = threadIdx.x;
    __shared__ float sx[DM];
    __shared__ float r4[4];
    const float4* x4 = (const float4*)(x + (size_t)t*DM);
    float4 xv = x4[tid];
    float ss = xv.x*xv.x + xv.y*xv.y + xv.z*xv.z + xv.w*xv.w;
    ss = blockReduceSum(ss);
    float rs = rsqrtf(ss / (float)DM + 1e-6f);
    float4 gv = ((const float4*)(goal + (size_t)t*DM))[tid];
    float4 wv = ((const float4*)n1w)[tid];
    float4 o;
    o.x = xv.x*rs*wv.x + gv.x;
    o.y = xv.y*rs*wv.y + gv.y;
    o.z = xv.z*rs*wv.z + gv.z;
    o.w = xv.w*rs*wv.w + gv.w;
    ((float4*)(g_xn + (size_t)t*DM))[tid] = o;
    ((float4*)sx)[tid] = o;
    __syncthreads();

    float acc = 0.f;
    if (tid < 148){
        const float* wp; int stride;
        if (tid < 4){ wp = rw + tid; stride = 4; }
        else        { wp = xw + (tid - 4); stride = 144; }
        #pragma unroll 4
        for (int k = 0; k < DM; k++) acc += sx[k] * wp[(size_t)k*stride];
    }
    if (tid < 4) r4[tid] = acc;
    else if (tid < 148) g_ssm[(size_t)t*144 + (tid-4)] = acc;
    __syncthreads();
    if (tid == 0){
        const float mix[4] = {0.5f, 0.2f, 0.15f, 0.15f};
        float m = r4[0];
        for (int e = 1; e < 4; e++) m = fmaxf(m, r4[e]);
        float e4[4], s = 0.f;
        for (int e = 0; e < 4; e++){ e4[e] = expf(r4[e]-m); s += e4[e]; }
        float ws = 0.f, wv2[4];
        for (int e = 0; e < 4; e++){ wv2[e] = e4[e]/s*mix[e]; ws += wv2[e]; }
        for (int e = 0; e < 4; e++) g_w[t*4+e] = wv2[e]/ws;
    }
}

// ---------------- K2: fused SSM scan + C-contraction. 1 warp per (b,h). ----------------
__global__ void k_scan(const float* __restrict__ Amat){
    int bh = blockIdx.x;            // 0..31
    int b = bh >> 4, h = bh & 15;
    int lane = threadIdx.x;         // 32 threads
    float a1 = Amat[h*NST + lane];
    float a2 = Amat[h*NST + lane + 32];
    float s1 = 0.f, s2 = 0.f;
    int base = b * LSEQ;
    for (int t = 0; t < LSEQ; t++){
        const float* row = g_ssm + (size_t)(base + t) * 144;
        float db = row[128 + h];
        float z1 = db + row[lane];
        float z2 = db + row[lane + 32];
        float dt1 = softplusf(z1);
        float dt2 = softplusf(z2);
        s1 = expf(dt1 * a1) * s1 + dt1 * dt1;
        s2 = expf(dt2 * a2) * s2 + dt2 * dt2;
        float p = s1 * row[64 + lane] + s2 * row[64 + lane + 32];
        #pragma unroll
        for (int o = 16; o > 0; o >>= 1) p += __shfl_xor_sync(0xffffffffu, p, o);
        if (lane == 0) g_y[(base + t)*NHH + h] = p;
    }
}

// ---------------- K3: yg = (y + xn*Dp) * sigmoid(gz + gate_b) ----------------
__global__ __launch_bounds__(256) void k_yg(const float* __restrict__ gate_b,
                                            const float* __restrict__ Dp){
    int t = blockIdx.x, tid = threadIdx.x;
    __shared__ float ys[NHH];
    if (tid < NHH) ys[tid] = g_y[t*NHH + tid];
    __syncthreads();
    size_t base = (size_t)t*DM;
    #pragma unroll
    for (int i = 0; i < 4; i++){
        int d = tid + (i << 8);
        int h = d >> 6;
        float gate = sigmoidf_(g_gz[base+d] + gate_b[d]);
        float yv = ys[h] + g_xn[base+d]*Dp[h];
        g_yg[base+d] = yv * gate;
    }
}

// ---------------- K4: per-head RMS + RoPE, in place. 1 warp per (token, head) ----------------
__global__ void k_rope(float* __restrict__ buf, const float* __restrict__ w, int nh){
    int gw = blockIdx.x * (blockDim.x >> 5) + (threadIdx.x >> 5);
    int lane = threadIdx.x & 31;
    int t = gw / nh, head = gw % nh;
    int pos = t & (LSEQ - 1);
    float* p = buf + ((size_t)t*nh + head)*HD;
    float u1 = p[lane], u2 = p[lane + 32];
    float ss = u1*u1 + u2*u2;
    #pragma unroll
    for (int o = 16; o > 0; o >>= 1) ss += __shfl_xor_sync(0xffffffffu, ss, o);
    float rs = rsqrtf(ss / 64.f + 1e-6f);
    u1 *= rs * w[lane];
    u2 *= rs * w[lane + 32];
    float ang = (float)pos * powf(10000.f, -(float)lane / 32.f);
    float c = cosf(ang), sn = sinf(ang);
    p[lane]      = u1*c - u2*sn;
    p[lane + 32] = u2*c + u1*sn;
}

// ---------------- K5: flash attention. grid (L/64, H, B), 256 threads ----------------
__global__ __launch_bounds__(256) void k_attn(){
    __shared__ float sQ[4096];   // 64x64
    __shared__ float sKP[4096];  // K tile, then reused as P tile
    __shared__ float sV[4096];
    int qt = blockIdx.x, h = blockIdx.y, b = blockIdx.z;
    int kvh = h >> 2;
    int tid = threadIdx.x;
    int r = tid >> 2, c4 = tid & 3;
    int q0 = qt * 64;

    for (int i = tid; i < 1024; i += 256){
        int row = i >> 4, cc = (i & 15) << 2;
        *(float4*)&sQ[row*64 + cc] =
            *(const float4*)&g_q[(((size_t)(b*LSEQ + q0 + row))*NHH + h)*HD + cc];
    }

    float m = -1e30f, lsum = 0.f;
    float acc[16];
    #pragma unroll
    for (int j = 0; j < 16; j++) acc[j] = 0.f;

    for (int kt = 0; kt < 16; kt++){
        __syncthreads();
        for (int i = tid; i < 1024; i += 256){
            int row = i >> 4, cc = (i & 15) << 2;
            size_t gk = (((size_t)(b*LSEQ + kt*64 + row))*NKV + kvh)*HD + cc;
            *(float4*)&sKP[row*64 + cc] = *(const float4*)&g_k[gk];
            *(float4*)&sV[row*64 + cc]  = *(const float4*)&g_v[gk];
        }
        __syncthreads();
        float s[16];
        #pragma unroll
        for (int j = 0; j < 16; j++){
            int c = c4*16 + j;
            float a2 = 0.f;
            #pragma unroll
            for (int kk = 0; kk < 64; kk += 4){
                float4 qa = *(const float4*)&sQ[r*64 + kk];
                float4 ka = *(const float4*)&sKP[c*64 + kk];
                a2 += qa.x*ka.x + qa.y*ka.y + qa.z*ka.z + qa.w*ka.w;
            }
            s[j] = a2 * 0.125f;
        }
        float tm = s[0];
        #pragma unroll
        for (int j = 1; j < 16; j++) tm = fmaxf(tm, s[j]);
        tm = fmaxf(tm, __shfl_xor_sync(0xffffffffu, tm, 1, 4));
        tm = fmaxf(tm, __shfl_xor_sync(0xffffffffu, tm, 2, 4));
        float nm = fmaxf(m, tm);
        float alpha = expf(m - nm);
        float ps = 0.f;
        #pragma unroll
        for (int j = 0; j < 16; j++){ s[j] = expf(s[j] - nm); ps += s[j]; }
        ps += __shfl_xor_sync(0xffffffffu, ps, 1, 4);
        ps += __shfl_xor_sync(0xffffffffu, ps, 2, 4);
        lsum = lsum*alpha + ps;
        m = nm;
        #pragma unroll
        for (int j = 0; j < 16; j++) acc[j] *= alpha;
        __syncthreads();                 // everyone done reading K from sKP
        #pragma unroll
        for (int j = 0; j < 16; j++) sKP[r*64 + c4*16 + j] = s[j];
        __syncthreads();
        for (int jj = 0; jj < 64; jj++){
            float p = sKP[r*64 + jj];
            const float* vrow = &sV[jj*64 + c4*16];
            #pragma unroll
            for (int dd = 0; dd < 16; dd += 4){
                float4 vv = *(const float4*)&vrow[dd];
                acc[dd]   += p*vv.x;
                acc[dd+1] += p*vv.y;
                acc[dd+2] += p*vv.z;
                acc[dd+3] += p*vv.w;
            }
        }
    }
    float inv = 1.f / lsum;
    size_t ob = ((size_t)(b*LSEQ + q0 + r)*NHH + h)*HD + c4*16;
    #pragma unroll
    for (int dd = 0; dd < 16; dd += 4){
        *(float4*)&g_attn[ob + dd] =
            make_float4(acc[dd]*inv, acc[dd+1]*inv, acc[dd+2]*inv, acc[dd+3]*inv);
    }
}

// ---------------- K6: conv branch dw + silu ----------------
__global__ void k_conv(const float* __restrict__ dw_w, const float* __restrict__ dw_b){
    int idx = blockIdx.x*blockDim.x + threadIdx.x;
    int t = idx >> 10, d = idx & 1023;
    int lp = t & (LSEQ - 1);
    float c = dw_b[d] + g_xn[idx]*dw_w[d*3 + 1];
    if (lp > 0)        c += g_xn[idx - DM]*dw_w[d*3 + 0];
    if (lp < LSEQ - 1) c += g_xn[idx + DM]*dw_w[d*3 + 2];
    g_dws[idx] = c * sigmoidf_(c);
}

// ---------------- K7: mix branches, write x2 (and to out) ----------------
__global__ void k_mix(const float* __restrict__ x, const float* __restrict__ mem,
                      const float* __restrict__ pw_b, float* __restrict__ out){
    int idx = blockIdx.x*blockDim.x + threadIdx.x;
    int t = idx >> 10, d = idx & 1023;
    const float* wt = g_w + t*4;
    float v = x[idx] + wt[0]*g_ssd[idx] + wt[1]*g_oattn[idx]
            + wt[2]*(g_conv[idx] + pw_b[d]) + wt[3]*mem[idx];
    g_x2[idx] = v;
    out[idx] = v;
}

// ---------------- K8a: reset per-expert counters ----------------
__global__ void k_reset(){
    if (threadIdx.x < NE) g_cnt[threadIdx.x] = 0;
}

// ---------------- K8: MoE gating: rms(x2)@moe_gate -> softmax -> top2; build token lists ----------------
__global__ __launch_bounds__(256) void k_moegate(const float* __restrict__ n2w,
                                                 const float* __restrict__ mg){
    int t = blockIdx.x, tid = threadIdx.x;
    float4 xv = ((const float4*)(g_x2 + (size_t)t*DM))[tid];
    float ss = xv.x*xv.x + xv.y*xv.y + xv.z*xv.z + xv.w*xv.w;
    ss = blockReduceSum(ss);
    float rs = rsqrtf(ss / (float)DM + 1e-6f);
    float4 wv = ((const float4*)n2w)[tid];
    float v0 = xv.x*rs*wv.x, v1 = xv.y*rs*wv.y, v2 = xv.z*rs*wv.z, v3 = xv.w*rs*wv.w;
    int kb = tid*4;
    const float4* mg4 = (const float4*)mg;   // row k of (1024,4) is one float4
    float4 m0 = mg4[kb], m1 = mg4[kb+1], m2 = mg4[kb+2], m3 = mg4[kb+3];
    float a0 = v0*m0.x + v1*m1.x + v2*m2.x + v3*m3.x;
    float a1 = v0*m0.y + v1*m1.y + v2*m2.y + v3*m3.y;
    float a2 = v0*m0.z + v1*m1.z + v2*m2.z + v3*m3.z;
    float a3 = v0*m0.w + v1*m1.w + v2*m2.w + v3*m3.w;
    a0 = blockReduceSum(a0);
    a1 = blockReduceSum(a1);
    a2 = blockReduceSum(a2);
    a3 = blockReduceSum(a3);
    if (tid == 0){
        float l[4] = {a0, a1, a2, a3};
        float mx = fmaxf(fmaxf(l[0], l[1]), fmaxf(l[2], l[3]));
        float e4[4], s = 0.f;
        for (int e = 0; e < 4; e++){ e4[e] = expf(l[e]-mx); s += e4[e]; }
        float gp[4];
        for (int e = 0; e < 4; e++) gp[e] = e4[e]/s;
        int i1 = 0;
        for (int e = 1; e < 4; e++) if (gp[e] > gp[i1]) i1 = e;
        int i2 = -1;
        for (int e = 0; e < 4; e++){
            if (e == i1) continue;
            if (i2 < 0 || gp[e] > gp[i2]) i2 = e;
        }
        float wf[4] = {0.f, 0.f, 0.f, 0.f};
        wf[i1] = gp[i1]; wf[i2] = gp[i2];
        for (int e = 0; e < 4; e++) g_wfull[t*4+e] = wf[e];
        int p1 = atomicAdd(&g_cnt[i1], 1);
        g_idx[i1*TT + p1] = t;
        int p2 = atomicAdd(&g_cnt[i2], 1);
        g_idx[i2*TT + p2] = t;
    }
}

// ---------------- K8b: gather assigned tokens into g_xg for expert e ----------------
__global__ __launch_bounds__(256) void k_gather(int e){
    int i = blockIdx.x;                 // gathered row
    if (i >= g_cnt[e]) return;
    int t = g_idx[e*TT + i];
    ((float4*)(g_xg + (size_t)i*DM))[threadIdx.x] =
        ((const float4*)(g_x2 + (size_t)t*DM))[threadIdx.x];
}

// ---------------- K9: MoE activation: hh = silu(a)*g (guarded by cnt) ----------------
__global__ void k_act(int e){
    int idx = blockIdx.x*blockDim.x + threadIdx.x;
    int t = idx >> 12, f = idx & 4095;
    if (t >= g_cnt[e]) return;
    float a = g_h1[(size_t)t*2*FF + f];
    float g = g_h1[(size_t)t*2*FF + FF + f];
    g_hh[idx] = a * sigmoidf_(a) * g;
}

// ---------------- K10: scatter expert output back into out ----------------
__global__ __launch_bounds__(256) void k_scatter(float* __restrict__ out,
                                                 const float* __restrict__ bias, int e){
    int i = blockIdx.x;
    if (i >= g_cnt[e]) return;
    int t = g_idx[e*TT + i];
    float w = g_wfull[t*4 + e];
    int tid = threadIdx.x;
    float4 eo = ((const float4*)(g_eo + (size_t)i*DM))[tid];
    float4 bv = ((const float4*)bias)[tid];
    float4 ov = ((float4*)(out + (size_t)t*DM))[tid];
    ov.x += w * (eo.x + bv.x);
    ov.y += w * (eo.y + bv.y);
    ov.z += w * (eo.z + bv.z);
    ov.w += w * (eo.w + bv.w);
    ((float4*)(out + (size_t)t*DM))[tid] = ov;
}

// ---------------- host ----------------
extern "C" void kernel_launch(void* const* d_in, const int* in_sizes, int n_in,
                              void* d_out, int out_size) {
    const float* x      = (const float*)d_in[0];
    const float* goal   = (const float*)d_in[1];
    const float* mem    = (const float*)d_in[2];
    const float* n1w    = (const float*)d_in[3];
    const float* n2w    = (const float*)d_in[4];
    const float* rw     = (const float*)d_in[5];
    const float* xw     = (const float*)d_in[6];
    const float* Amat   = (const float*)d_in[7];
    const float* Dp     = (const float*)d_in[8];
    const float* gate_w = (const float*)d_in[9];
    const float* gate_b = (const float*)d_in[10];
    const float* ssd_o  = (const float*)d_in[11];
    const float* q_w    = (const float*)d_in[12];
    const float* k_w    = (const float*)d_in[13];
    const float* v_w    = (const float*)d_in[14];
    const float* o_w    = (const float*)d_in[15];
    const float* qn     = (const float*)d_in[16];
    const float* kn     = (const float*)d_in[17];
    const float* dw_w   = (const float*)d_in[18];
    const float* dw_b   = (const float*)d_in[19];
    const float* pw_w   = (const float*)d_in[20];
    const float* pw_b   = (const float*)d_in[21];
    const float* mg     = (const float*)d_in[22];
    const float* ew1    = (const float*)d_in[23];
    const float* ew2    = (const float*)d_in[24];
    const float* elw    = (const float*)d_in[25];
    const float* elb    = (const float*)d_in[26];
    float* out = (float*)d_out;

    float *p_xn, *p_gz, *p_yg, *p_ssd, *p_q, *p_k, *p_v, *p_attn, *p_oattn,
          *p_dws, *p_conv, *p_x2, *p_xg, *p_h1, *p_hh, *p_h2, *p_eo;
    int *p_cnt;
    cudaGetSymbolAddress((void**)&p_xn,   g_xn);
    cudaGetSymbolAddress((void**)&p_gz,   g_gz);
    cudaGetSymbolAddress((void**)&p_yg,   g_yg);
    cudaGetSymbolAddress((void**)&p_ssd,  g_ssd);
    cudaGetSymbolAddress((void**)&p_q,    g_q);
    cudaGetSymbolAddress((void**)&p_k,    g_k);
    cudaGetSymbolAddress((void**)&p_v,    g_v);
    cudaGetSymbolAddress((void**)&p_attn, g_attn);
    cudaGetSymbolAddress((void**)&p_oattn,g_oattn);
    cudaGetSymbolAddress((void**)&p_dws,  g_dws);
    cudaGetSymbolAddress((void**)&p_conv, g_conv);
    cudaGetSymbolAddress((void**)&p_x2,   g_x2);
    cudaGetSymbolAddress((void**)&p_xg,   g_xg);
    cudaGetSymbolAddress((void**)&p_h1,   g_h1);
    cudaGetSymbolAddress((void**)&p_hh,   g_hh);
    cudaGetSymbolAddress((void**)&p_h2,   g_h2);
    cudaGetSymbolAddress((void**)&p_eo,   g_eo);
    cudaGetSymbolAddress((void**)&p_cnt,  g_cnt);

    // 1. pre: xn, router weights, ssm projection
    k_pre<<<TT, 256>>>(x, goal, n1w, rw, xw);
    // 2. fused SSM scan + C contraction
    k_scan<<<NHH*2, 32>>>(Amat);
    // 3. gate projection + yg
    sgemm<<<dim3(DM/128, TT/128), 256>>>(p_xn, gate_w, p_gz, TT, DM, DM, nullptr);
    k_yg<<<TT, 256>>>(gate_b, Dp);
    // 4. ssd output projection
    sgemm<<<dim3(DM/128, TT/128), 256>>>(p_yg, ssd_o, p_ssd, TT, DM, DM, nullptr);
    // 5. attention: q/k/v projections, rms+rope, flash attn, out proj
    sgemm<<<dim3(DM/128, TT/128), 256>>>(p_xn, q_w, p_q, TT, DM, DM, nullptr);
    sgemm<<<dim3(2, TT/128), 256>>>(p_xn, k_w, p_k, TT, NKV*HD, DM, nullptr);
    sgemm<<<dim3(2, TT/128), 256>>>(p_xn, v_w, p_v, TT, NKV*HD, DM, nullptr);
    k_rope<<<TT*NHH/4, 128>>>(p_q, qn, NHH);
    k_rope<<<TT*NKV/4, 128>>>(p_k, kn, NKV);
    k_attn<<<dim3(LSEQ/64, NHH, 2), 256>>>();
    sgemm<<<dim3(DM/128, TT/128), 256>>>(p_attn, o_w, p_oattn, TT, DM, DM, nullptr);
    // 6. conv branch
    k_conv<<<TT*DM/256, 256>>>(dw_w, dw_b);
    sgemm<<<dim3(DM/128, TT/128), 256>>>(p_dws, pw_w, p_conv, TT, DM, DM, nullptr);
    // 7. mix -> x2 (also seeds out)
    k_mix<<<TT*DM/256, 256>>>(x, mem, pw_b, out);
    // 8. MoE gating + token lists
    k_reset<<<1, 32>>>();
    k_moegate<<<TT, 256>>>(n2w, mg);
    // 9. MoE experts — top-2 sparse + tf32 tensor cores (no routing decisions
    //    downstream of these GEMMs, so tf32 precision is safe here).
    for (int e = 0; e < 4; e++){
        k_gather<<<TT, 256>>>(e);
        gemm_tf32<<<dim3(2*FF/128, TT/128), 256>>>(p_xg, ew1 + (size_t)e*DM*2*FF, p_h1, TT, 2*FF, DM, p_cnt);
        k_act<<<TT*FF/256, 256>>>(e);
        gemm_tf32<<<dim3(DM/128, TT/128), 256>>>(p_hh, ew2 + (size_t)e*FF*DM, p_h2, TT, DM, FF, p_cnt);
        gemm_tf32<<<dim3(DM/128, TT/128), 256>>>(p_h2, elw + (size_t)e*DM*DM, p_eo, TT, DM, DM, p_cnt);
        k_scatter<<<TT, 256>>>(out, elb + (size_t)e*DM, e);
    }
}

// round 15
// speedup vs baseline: 1.9837x; 1.2487x over previous
#include <cuda_runtime.h>
#include <math.h>

// Problem constants
#define TT   2048      // B*L tokens
#define DM   1024
#define LSEQ 1024
#define NHH  16
#define NKV  4
#define HD   64
#define NST  64        // SSM state dim N
#define FF   4096
#define NE   4

// ---------------- scratch (static device globals; no allocations) ----------------
__device__ float g_xn[TT*DM];
__device__ float g_w[TT*4];
__device__ float g_ssm[TT*144];
__device__ float g_y[TT*NHH];
__device__ float g_gz[TT*DM];
__device__ float g_yg[TT*DM];
__device__ float g_ssd[TT*DM];
__device__ float g_q[TT*DM];
__device__ float g_k[TT*NKV*HD];
__device__ float g_v[TT*NKV*HD];
__device__ float g_attn[TT*DM];
__device__ float g_oattn[TT*DM];
__device__ float g_dws[TT*DM];
__device__ float g_conv[TT*DM];
__device__ float g_x2[TT*DM];
__device__ float g_wfull[TT*4];
__device__ float g_xg[(size_t)NE*TT*DM];
__device__ float g_h1[(size_t)NE*TT*2*FF];
__device__ float g_hh[(size_t)NE*TT*FF];
__device__ float g_h2[(size_t)NE*TT*DM];
__device__ float g_eo[(size_t)NE*TT*DM];
__device__ int   g_idx[NE*TT];
__device__ int   g_pos[NE*TT];
__device__ int   g_cnt[NE];

// ---------------- helpers ----------------
__device__ __forceinline__ float blockReduceSum(float v){
    __shared__ float red[33];
    int lane = threadIdx.x & 31, wid = threadIdx.x >> 5;
    __syncthreads();
    #pragma unroll
    for (int o = 16; o > 0; o >>= 1) v += __shfl_xor_sync(0xffffffffu, v, o);
    if (lane == 0) red[wid] = v;
    __syncthreads();
    if (wid == 0){
        float s = (lane < (int)(blockDim.x >> 5)) ? red[lane] : 0.f;
        #pragma unroll
        for (int o = 16; o > 0; o >>= 1) s += __shfl_xor_sync(0xffffffffu, s, o);
        if (lane == 0) red[32] = s;
    }
    __syncthreads();
    return red[32];
}

__device__ __forceinline__ float softplusf(float z){
    return (z > 20.f) ? z : log1pf(expf(z));
}
__device__ __forceinline__ float sigmoidf_(float z){
    return 1.f / (1.f + expf(-z));
}
__device__ __forceinline__ unsigned f2tf(float x){
    unsigned r; asm("cvt.rna.tf32.f32 %0, %1;" : "=r"(r) : "f"(x)); return r;
}

#define MMA_TF32(cc, a0, a1, a2, a3, b0, b1)                                  \
    asm volatile(                                                             \
        "mma.sync.aligned.m16n8k8.row.col.f32.tf32.tf32.f32 "                 \
        "{%0,%1,%2,%3}, {%4,%5,%6,%7}, {%8,%9}, {%0,%1,%2,%3};"               \
        : "+f"((cc)[0]), "+f"((cc)[1]), "+f"((cc)[2]), "+f"((cc)[3])          \
        : "r"(a0), "r"(a1), "r"(a2), "r"(a3), "r"(b0), "r"(b1))

struct GArgs {
    const float* A[5];
    const float* B[5];
    float*       C[5];
    int          N[5];
};

// ---------------- TF32-SPLIT multi-GEMM (fp32-accurate, tensor cores) ----------------
// C[M,N] = A[M,K] @ B[K,N] with x=hi+lo split: hi*hi + hi*lo + lo*hi (lo*lo dropped,
// <=2^-22 relative -> fp32-grade). BM=BN=128, BK=16, single-buffered smem,
// 8 warps, warp tile 64x32, same fragment layout as gemm_tf32 (HW-verified R5).
__global__ __launch_bounds__(256) void gemm_split_multi(GArgs args, int K){
    int z = blockIdx.z;
    int N = args.N[z];
    if ((int)(blockIdx.x * 128) >= N) return;
    const float* A = args.A[z];
    const float* B = args.B[z];
    float*       C = args.C[z];

    __shared__ unsigned Ah[128][20], Al[128][20];   // [m][k] pitch 20
    __shared__ unsigned Bh[16][136], Bl[16][136];   // [k][n] pitch 136
    int tid = threadIdx.x;
    int lane = tid & 31, warp = tid >> 5;
    int wm = (warp & 1) << 6;
    int wn = (warp >> 1) << 5;
    int q = lane >> 2, r = lane & 3;

    const float* Ab = A + (size_t)blockIdx.y * 128 * K;
    const float* Bb = B + blockIdx.x * 128;

    int arow0 = tid >> 2,  acol = (tid & 3) << 2;
    int arow1 = arow0 + 64;
    int brow0 = tid >> 5,  bcol = (tid & 31) << 2;
    int brow1 = brow0 + 8;

    float c[16][4];
    #pragma unroll
    for (int i = 0; i < 16; i++)
        #pragma unroll
        for (int j = 0; j < 4; j++) c[i][j] = 0.f;

#define SPLA(rw, cl, val) { unsigned _h = f2tf(val); Ah[rw][cl] = _h; Al[rw][cl] = f2tf((val) - __uint_as_float(_h)); }
#define SPLB(rw, cl, val) { unsigned _h = f2tf(val); Bh[rw][cl] = _h; Bl[rw][cl] = f2tf((val) - __uint_as_float(_h)); }

    for (int kt = 0; kt < K; kt += 16){
        float4 av0 = *(const float4*)(Ab + (size_t)arow0*K + kt + acol);
        float4 av1 = *(const float4*)(Ab + (size_t)arow1*K + kt + acol);
        float4 bv0 = *(const float4*)(Bb + (size_t)(brow0 + kt)*N + bcol);
        float4 bv1 = *(const float4*)(Bb + (size_t)(brow1 + kt)*N + bcol);
        SPLA(arow0, acol+0, av0.x); SPLA(arow0, acol+1, av0.y);
        SPLA(arow0, acol+2, av0.z); SPLA(arow0, acol+3, av0.w);
        SPLA(arow1, acol+0, av1.x); SPLA(arow1, acol+1, av1.y);
        SPLA(arow1, acol+2, av1.z); SPLA(arow1, acol+3, av1.w);
        SPLB(brow0, bcol+0, bv0.x); SPLB(brow0, bcol+1, bv0.y);
        SPLB(brow0, bcol+2, bv0.z); SPLB(brow0, bcol+3, bv0.w);
        SPLB(brow1, bcol+0, bv1.x); SPLB(brow1, bcol+1, bv1.y);
        SPLB(brow1, bcol+2, bv1.z); SPLB(brow1, bcol+3, bv1.w);
        __syncthreads();

        #pragma unroll
        for (int ks = 0; ks < 16; ks += 8){
            unsigned ah[4][4], al[4][4], bh2[4][2], bl2[4][2];
            #pragma unroll
            for (int mf = 0; mf < 4; mf++){
                int m0 = wm + mf*16;
                ah[mf][0] = Ah[m0 + q    ][ks + r    ];
                ah[mf][1] = Ah[m0 + q + 8][ks + r    ];
                ah[mf][2] = Ah[m0 + q    ][ks + r + 4];
                ah[mf][3] = Ah[m0 + q + 8][ks + r + 4];
                al[mf][0] = Al[m0 + q    ][ks + r    ];
                al[mf][1] = Al[m0 + q + 8][ks + r    ];
                al[mf][2] = Al[m0 + q    ][ks + r + 4];
                al[mf][3] = Al[m0 + q + 8][ks + r + 4];
            }
            #pragma unroll
            for (int nf = 0; nf < 4; nf++){
                int n0 = wn + nf*8;
                bh2[nf][0] = Bh[ks + r    ][n0 + q];
                bh2[nf][1] = Bh[ks + r + 4][n0 + q];
                bl2[nf][0] = Bl[ks + r    ][n0 + q];
                bl2[nf][1] = Bl[ks + r + 4][n0 + q];
            }
            #pragma unroll
            for (int mf = 0; mf < 4; mf++)
                #pragma unroll
                for (int nf = 0; nf < 4; nf++){
                    float* cc = c[mf*4 + nf];
                    MMA_TF32(cc, ah[mf][0], ah[mf][1], ah[mf][2], ah[mf][3],
                             bh2[nf][0], bh2[nf][1]);
                    MMA_TF32(cc, ah[mf][0], ah[mf][1], ah[mf][2], ah[mf][3],
                             bl2[nf][0], bl2[nf][1]);
                    MMA_TF32(cc, al[mf][0], al[mf][1], al[mf][2], al[mf][3],
                             bh2[nf][0], bh2[nf][1]);
                }
        }
        __syncthreads();
    }
#undef SPLA
#undef SPLB
    int rowbase = blockIdx.y*128 + wm + q;
    int colbase = blockIdx.x*128 + wn + (r << 1);
    #pragma unroll
    for (int mf = 0; mf < 4; mf++){
        #pragma unroll
        for (int nf = 0; nf < 4; nf++){
            float* cc = c[mf*4 + nf];
            int row0 = rowbase + mf*16;
            int col  = colbase + nf*8;
            *(float2*)&C[(size_t)row0*N + col]      = make_float2(cc[0], cc[1]);
            *(float2*)&C[(size_t)(row0+8)*N + col]  = make_float2(cc[2], cc[3]);
        }
    }
}

// ---------------- TF32 tensor-core GEMM, expert-batched via blockIdx.z ----------------
// BM=BN=128, BK=16, 256 threads (8 warps), warp tile 64x32, m16n8k8 mma.
__global__ __launch_bounds__(256) void gemm_tf32(const float* __restrict__ A0,
                                                 const float* __restrict__ B0,
                                                 float* __restrict__ C0,
                                                 int N, int K,
                                                 size_t sA, size_t sB, size_t sC){
    int e = blockIdx.z;
    if ((int)(blockIdx.y * 128) >= g_cnt[e]) return;
    const float* A = A0 + (size_t)e * sA;
    const float* B = B0 + (size_t)e * sB;
    float*       C = C0 + (size_t)e * sC;

    __shared__ unsigned As[2][128][20];
    __shared__ unsigned Bs[2][16][136];
    int tid = threadIdx.x;
    int lane = tid & 31, warp = tid >> 5;
    int wm = (warp & 1) << 6;
    int wn = (warp >> 1) << 5;
    int q = lane >> 2, r = lane & 3;

    const float* Ab = A + (size_t)blockIdx.y * 128 * K;
    const float* Bb = B + (size_t)blockIdx.x * 128;

    int arow0 = tid >> 2,        acol = (tid & 3) << 2;
    int arow1 = arow0 + 64;
    int brow0 = tid >> 5,        bcol = (tid & 31) << 2;
    int brow1 = brow0 + 8;

    float c[16][4];
    #pragma unroll
    for (int i = 0; i < 16; i++)
        #pragma unroll
        for (int j = 0; j < 4; j++) c[i][j] = 0.f;

    {
        float4 av0 = *(const float4*)(Ab + (size_t)arow0*K + acol);
        float4 av1 = *(const float4*)(Ab + (size_t)arow1*K + acol);
        float4 bv0 = *(const float4*)(Bb + (size_t)brow0*N + bcol);
        float4 bv1 = *(const float4*)(Bb + (size_t)brow1*N + bcol);
        As[0][arow0][acol+0]=f2tf(av0.x); As[0][arow0][acol+1]=f2tf(av0.y);
        As[0][arow0][acol+2]=f2tf(av0.z); As[0][arow0][acol+3]=f2tf(av0.w);
        As[0][arow1][acol+0]=f2tf(av1.x); As[0][arow1][acol+1]=f2tf(av1.y);
        As[0][arow1][acol+2]=f2tf(av1.z); As[0][arow1][acol+3]=f2tf(av1.w);
        Bs[0][brow0][bcol+0]=f2tf(bv0.x); Bs[0][brow0][bcol+1]=f2tf(bv0.y);
        Bs[0][brow0][bcol+2]=f2tf(bv0.z); Bs[0][brow0][bcol+3]=f2tf(bv0.w);
        Bs[0][brow1][bcol+0]=f2tf(bv1.x); Bs[0][brow1][bcol+1]=f2tf(bv1.y);
        Bs[0][brow1][bcol+2]=f2tf(bv1.z); Bs[0][brow1][bcol+3]=f2tf(bv1.w);
    }
    __syncthreads();

    int buf = 0;
    for (int kt = 16; kt <= K; kt += 16){
        float4 av0, av1, bv0, bv1;
        bool more = (kt < K);
        if (more){
            av0 = *(const float4*)(Ab + (size_t)arow0*K + kt + acol);
            av1 = *(const float4*)(Ab + (size_t)arow1*K + kt + acol);
            bv0 = *(const float4*)(Bb + (size_t)(brow0 + kt)*N + bcol);
            bv1 = *(const float4*)(Bb + (size_t)(brow1 + kt)*N + bcol);
        }
        #pragma unroll
        for (int ks = 0; ks < 16; ks += 8){
            unsigned af[4][4], bf[4][2];
            #pragma unroll
            for (int mf = 0; mf < 4; mf++){
                int m0 = wm + mf*16;
                af[mf][0] = As[buf][m0 + q    ][ks + r    ];
                af[mf][1] = As[buf][m0 + q + 8][ks + r    ];
                af[mf][2] = As[buf][m0 + q    ][ks + r + 4];
                af[mf][3] = As[buf][m0 + q + 8][ks + r + 4];
            }
            #pragma unroll
            for (int nf = 0; nf < 4; nf++){
                int n0 = wn + nf*8;
                bf[nf][0] = Bs[buf][ks + r    ][n0 + q];
                bf[nf][1] = Bs[buf][ks + r + 4][n0 + q];
            }
            #pragma unroll
            for (int mf = 0; mf < 4; mf++)
                #pragma unroll
                for (int nf = 0; nf < 4; nf++){
                    float* cc = c[mf*4 + nf];
                    MMA_TF32(cc, af[mf][0], af[mf][1], af[mf][2], af[mf][3],
                             bf[nf][0], bf[nf][1]);
                }
        }
        if (more){
            int nb = buf ^ 1;
            As[nb][arow0][acol+0]=f2tf(av0.x); As[nb][arow0][acol+1]=f2tf(av0.y);
            As[nb][arow0][acol+2]=f2tf(av0.z); As[nb][arow0][acol+3]=f2tf(av0.w);
            As[nb][arow1][acol+0]=f2tf(av1.x); As[nb][arow1][acol+1]=f2tf(av1.y);
            As[nb][arow1][acol+2]=f2tf(av1.z); As[nb][arow1][acol+3]=f2tf(av1.w);
            Bs[nb][brow0][bcol+0]=f2tf(bv0.x); Bs[nb][brow0][bcol+1]=f2tf(bv0.y);
            Bs[nb][brow0][bcol+2]=f2tf(bv0.z); Bs[nb][brow0][bcol+3]=f2tf(bv0.w);
            Bs[nb][brow1][bcol+0]=f2tf(bv1.x); Bs[nb][brow1][bcol+1]=f2tf(bv1.y);
            Bs[nb][brow1][bcol+2]=f2tf(bv1.z); Bs[nb][brow1][bcol+3]=f2tf(bv1.w);
            __syncthreads();
            buf = nb;
        }
    }
    int rowbase = blockIdx.y*128 + wm + q;
    int colbase = blockIdx.x*128 + wn + (r << 1);
    #pragma unroll
    for (int mf = 0; mf < 4; mf++){
        #pragma unroll
        for (int nf = 0; nf < 4; nf++){
            float* cc = c[mf*4 + nf];
            int row0 = rowbase + mf*16;
            int col  = colbase + nf*8;
            *(float2*)&C[(size_t)row0*N + col]      = make_float2(cc[0], cc[1]);
            *(float2*)&C[(size_t)(row0+8)*N + col]  = make_float2(cc[2], cc[3]);
        }
    }
}

// ---------------- K1: xn = rms(x)*n1w + goal; router weights w; ssm = xn @ xproj ----------------
__global__ __launch_bounds__(256) void k_pre(const float* __restrict__ x,
                                             const float* __restrict__ goal,
                                             const float* __restrict__ n1w,
                                             const float* __restrict__ rw,
                                             const float* __restrict__ xw){
    int t = blockIdx.x, tid = threadIdx.x;
    __shared__ float sx[DM];
    __shared__ float r4[4];
    const float4* x4 = (const float4*)(x + (size_t)t*DM);
    float4 xv = x4[tid];
    float ss = xv.x*xv.x + xv.y*xv.y + xv.z*xv.z + xv.w*xv.w;
    ss = blockReduceSum(ss);
    float rs = rsqrtf(ss / (float)DM + 1e-6f);
    float4 gv = ((const float4*)(goal + (size_t)t*DM))[tid];
    float4 wv = ((const float4*)n1w)[tid];
    float4 o;
    o.x = xv.x*rs*wv.x + gv.x;
    o.y = xv.y*rs*wv.y + gv.y;
    o.z = xv.z*rs*wv.z + gv.z;
    o.w = xv.w*rs*wv.w + gv.w;
    ((float4*)(g_xn + (size_t)t*DM))[tid] = o;
    ((float4*)sx)[tid] = o;
    __syncthreads();

    float acc = 0.f;
    if (tid < 148){
        const float* wp; int stride;
        if (tid < 4){ wp = rw + tid; stride = 4; }
        else        { wp = xw + (tid - 4); stride = 144; }
        #pragma unroll 4
        for (int k = 0; k < DM; k++) acc += sx[k] * wp[(size_t)k*stride];
    }
    if (tid < 4) r4[tid] = acc;
    else if (tid < 148) g_ssm[(size_t)t*144 + (tid-4)] = acc;
    __syncthreads();
    if (tid == 0){
        const float mix[4] = {0.5f, 0.2f, 0.15f, 0.15f};
        float m = r4[0];
        for (int e = 1; e < 4; e++) m = fmaxf(m, r4[e]);
        float e4[4], s = 0.f;
        for (int e = 0; e < 4; e++){ e4[e] = expf(r4[e]-m); s += e4[e]; }
        float ws = 0.f, wv2[4];
        for (int e = 0; e < 4; e++){ wv2[e] = e4[e]/s*mix[e]; ws += wv2[e]; }
        for (int e = 0; e < 4; e++) g_w[t*4+e] = wv2[e]/ws;
    }
}

// ---------------- K2: fused SSM scan + C-contraction. 1 warp per (b,h). ----------------
__global__ void k_scan(const float* __restrict__ Amat){
    int bh = blockIdx.x;
    int b = bh >> 4, h = bh & 15;
    int lane = threadIdx.x;
    float a1 = Amat[h*NST + lane];
    float a2 = Amat[h*NST + lane + 32];
    float s1 = 0.f, s2 = 0.f;
    int base = b * LSEQ;
    for (int t = 0; t < LSEQ; t++){
        const float* row = g_ssm + (size_t)(base + t) * 144;
        float db = row[128 + h];
        float z1 = db + row[lane];
        float z2 = db + row[lane + 32];
        float dt1 = softplusf(z1);
        float dt2 = softplusf(z2);
        s1 = expf(dt1 * a1) * s1 + dt1 * dt1;
        s2 = expf(dt2 * a2) * s2 + dt2 * dt2;
        float p = s1 * row[64 + lane] + s2 * row[64 + lane + 32];
        #pragma unroll
        for (int o = 16; o > 0; o >>= 1) p += __shfl_xor_sync(0xffffffffu, p, o);
        if (lane == 0) g_y[(base + t)*NHH + h] = p;
    }
}

// ---------------- K3: yg = (y + xn*Dp) * sigmoid(gz + gate_b) ----------------
__global__ __launch_bounds__(256) void k_yg(const float* __restrict__ gate_b,
                                            const float* __restrict__ Dp){
    int t = blockIdx.x, tid = threadIdx.x;
    __shared__ float ys[NHH];
    if (tid < NHH) ys[tid] = g_y[t*NHH + tid];
    __syncthreads();
    size_t base = (size_t)t*DM;
    #pragma unroll
    for (int i = 0; i < 4; i++){
        int d = tid + (i << 8);
        int h = d >> 6;
        float gate = sigmoidf_(g_gz[base+d] + gate_b[d]);
        float yv = ys[h] + g_xn[base+d]*Dp[h];
        g_yg[base+d] = yv * gate;
    }
}

// ---------------- K4: per-head RMS + RoPE, in place. 1 warp per (token, head) ----------------
__global__ void k_rope(float* __restrict__ buf, const float* __restrict__ w, int nh){
    int gw = blockIdx.x * (blockDim.x >> 5) + (threadIdx.x >> 5);
    int lane = threadIdx.x & 31;
    int t = gw / nh, head = gw % nh;
    int pos = t & (LSEQ - 1);
    float* p = buf + ((size_t)t*nh + head)*HD;
    float u1 = p[lane], u2 = p[lane + 32];
    float ss = u1*u1 + u2*u2;
    #pragma unroll
    for (int o = 16; o > 0; o >>= 1) ss += __shfl_xor_sync(0xffffffffu, ss, o);
    float rs = rsqrtf(ss / 64.f + 1e-6f);
    u1 *= rs * w[lane];
    u2 *= rs * w[lane + 32];
    float ang = (float)pos * powf(10000.f, -(float)lane / 32.f);
    float c = cosf(ang), sn = sinf(ang);
    p[lane]      = u1*c - u2*sn;
    p[lane + 32] = u2*c + u1*sn;
}

// ---------------- K5: flash attention. grid (L/64, H, B), 256 threads ----------------
__global__ __launch_bounds__(256) void k_attn(){
    __shared__ float sQ[4096];
    __shared__ float sKP[4096];
    __shared__ float sV[4096];
    int qt = blockIdx.x, h = blockIdx.y, b = blockIdx.z;
    int kvh = h >> 2;
    int tid = threadIdx.x;
    int r = tid >> 2, c4 = tid & 3;
    int q0 = qt * 64;

    for (int i = tid; i < 1024; i += 256){
        int row = i >> 4, cc = (i & 15) << 2;
        *(float4*)&sQ[row*64 + cc] =
            *(const float4*)&g_q[(((size_t)(b*LSEQ + q0 + row))*NHH + h)*HD + cc];
    }

    float m = -1e30f, lsum = 0.f;
    float acc[16];
    #pragma unroll
    for (int j = 0; j < 16; j++) acc[j] = 0.f;

    for (int kt = 0; kt < 16; kt++){
        __syncthreads();
        for (int i = tid; i < 1024; i += 256){
            int row = i >> 4, cc = (i & 15) << 2;
            size_t gk = (((size_t)(b*LSEQ + kt*64 + row))*NKV + kvh)*HD + cc;
            *(float4*)&sKP[row*64 + cc] = *(const float4*)&g_k[gk];
            *(float4*)&sV[row*64 + cc]  = *(const float4*)&g_v[gk];
        }
        __syncthreads();
        float s[16];
        #pragma unroll
        for (int j = 0; j < 16; j++){
            int c = c4*16 + j;
            float a2 = 0.f;
            #pragma unroll
            for (int kk = 0; kk < 64; kk += 4){
                float4 qa = *(const float4*)&sQ[r*64 + kk];
                float4 ka = *(const float4*)&sKP[c*64 + kk];
                a2 += qa.x*ka.x + qa.y*ka.y + qa.z*ka.z + qa.w*ka.w;
            }
            s[j] = a2 * 0.125f;
        }
        float tm = s[0];
        #pragma unroll
        for (int j = 1; j < 16; j++) tm = fmaxf(tm, s[j]);
        tm = fmaxf(tm, __shfl_xor_sync(0xffffffffu, tm, 1, 4));
        tm = fmaxf(tm, __shfl_xor_sync(0xffffffffu, tm, 2, 4));
        float nm = fmaxf(m, tm);
        float alpha = expf(m - nm);
        float ps = 0.f;
        #pragma unroll
        for (int j = 0; j < 16; j++){ s[j] = expf(s[j] - nm); ps += s[j]; }
        ps += __shfl_xor_sync(0xffffffffu, ps, 1, 4);
        ps += __shfl_xor_sync(0xffffffffu, ps, 2, 4);
        lsum = lsum*alpha + ps;
        m = nm;
        #pragma unroll
        for (int j = 0; j < 16; j++) acc[j] *= alpha;
        __syncthreads();
        #pragma unroll
        for (int j = 0; j < 16; j++) sKP[r*64 + c4*16 + j] = s[j];
        __syncthreads();
        for (int jj = 0; jj < 64; jj++){
            float p = sKP[r*64 + jj];
            const float* vrow = &sV[jj*64 + c4*16];
            #pragma unroll
            for (int dd = 0; dd < 16; dd += 4){
                float4 vv = *(const float4*)&vrow[dd];
                acc[dd]   += p*vv.x;
                acc[dd+1] += p*vv.y;
                acc[dd+2] += p*vv.z;
                acc[dd+3] += p*vv.w;
            }
        }
    }
    float inv = 1.f / lsum;
    size_t ob = ((size_t)(b*LSEQ + q0 + r)*NHH + h)*HD + c4*16;
    #pragma unroll
    for (int dd = 0; dd < 16; dd += 4){
        *(float4*)&g_attn[ob + dd] =
            make_float4(acc[dd]*inv, acc[dd+1]*inv, acc[dd+2]*inv, acc[dd+3]*inv);
    }
}

// ---------------- K6: conv branch dw + silu ----------------
__global__ void k_conv(const float* __restrict__ dw_w, const float* __restrict__ dw_b){
    int idx = blockIdx.x*blockDim.x + threadIdx.x;
    int t = idx >> 10, d = idx & 1023;
    int lp = t & (LSEQ - 1);
    float c = dw_b[d] + g_xn[idx]*dw_w[d*3 + 1];
    if (lp > 0)        c += g_xn[idx - DM]*dw_w[d*3 + 0];
    if (lp < LSEQ - 1) c += g_xn[idx + DM]*dw_w[d*3 + 2];
    g_dws[idx] = c * sigmoidf_(c);
}

// ---------------- K7: mix branches, write x2 (and to out) ----------------
__global__ void k_mix(const float* __restrict__ x, const float* __restrict__ mem,
                      const float* __restrict__ pw_b, float* __restrict__ out){
    int idx = blockIdx.x*blockDim.x + threadIdx.x;
    int t = idx >> 10, d = idx & 1023;
    const float* wt = g_w + t*4;
    float v = x[idx] + wt[0]*g_ssd[idx] + wt[1]*g_oattn[idx]
            + wt[2]*(g_conv[idx] + pw_b[d]) + wt[3]*mem[idx];
    g_x2[idx] = v;
    out[idx] = v;
}

// ---------------- K8a: reset per-expert counters ----------------
__global__ void k_reset(){
    if (threadIdx.x < NE) g_cnt[threadIdx.x] = 0;
}

// ---------------- K8: MoE gating; top-2 lists + inverse map ----------------
__global__ __launch_bounds__(256) void k_moegate(const float* __restrict__ n2w,
                                                 const float* __restrict__ mg){
    int t = blockIdx.x, tid = threadIdx.x;
    float4 xv = ((const float4*)(g_x2 + (size_t)t*DM))[tid];
    float ss = xv.x*xv.x + xv.y*xv.y + xv.z*xv.z + xv.w*xv.w;
    ss = blockReduceSum(ss);
    float rs = rsqrtf(ss / (float)DM + 1e-6f);
    float4 wv = ((const float4*)n2w)[tid];
    float v0 = xv.x*rs*wv.x, v1 = xv.y*rs*wv.y, v2 = xv.z*rs*wv.z, v3 = xv.w*rs*wv.w;
    int kb = tid*4;
    const float4* mg4 = (const float4*)mg;
    float4 m0 = mg4[kb], m1 = mg4[kb+1], m2 = mg4[kb+2], m3 = mg4[kb+3];
    float a0 = v0*m0.x + v1*m1.x + v2*m2.x + v3*m3.x;
    float a1 = v0*m0.y + v1*m1.y + v2*m2.y + v3*m3.y;
    float a2 = v0*m0.z + v1*m1.z + v2*m2.z + v3*m3.z;
    float a3 = v0*m0.w + v1*m1.w + v2*m2.w + v3*m3.w;
    a0 = blockReduceSum(a0);
    a1 = blockReduceSum(a1);
    a2 = blockReduceSum(a2);
    a3 = blockReduceSum(a3);
    if (tid == 0){
        float l[4] = {a0, a1, a2, a3};
        float mx = fmaxf(fmaxf(l[0], l[1]), fmaxf(l[2], l[3]));
        float e4[4], s = 0.f;
        for (int e = 0; e < 4; e++){ e4[e] = expf(l[e]-mx); s += e4[e]; }
        float gp[4];
        for (int e = 0; e < 4; e++) gp[e] = e4[e]/s;
        int i1 = 0;
        for (int e = 1; e < 4; e++) if (gp[e] > gp[i1]) i1 = e;
        int i2 = -1;
        for (int e = 0; e < 4; e++){
            if (e == i1) continue;
            if (i2 < 0 || gp[e] > gp[i2]) i2 = e;
        }
        float wf[4] = {0.f, 0.f, 0.f, 0.f};
        wf[i1] = gp[i1]; wf[i2] = gp[i2];
        for (int e = 0; e < 4; e++) g_wfull[t*4+e] = wf[e];
        int p1 = atomicAdd(&g_cnt[i1], 1);
        g_idx[i1*TT + p1] = t;
        g_pos[i1*TT + t]  = p1;
        int p2 = atomicAdd(&g_cnt[i2], 1);
        g_idx[i2*TT + p2] = t;
        g_pos[i2*TT + t]  = p2;
    }
}

// ---------------- K8b: gather, all experts. grid (TT, NE) ----------------
__global__ __launch_bounds__(256) void k_gather(){
    int i = blockIdx.x, e = blockIdx.y;
    if (i >= g_cnt[e]) return;
    int t = g_idx[e*TT + i];
    ((float4*)(g_xg + (size_t)(e*TT + i)*DM))[threadIdx.x] =
        ((const float4*)(g_x2 + (size_t)t*DM))[threadIdx.x];
}

// ---------------- K9: MoE activation, all experts. grid (TT*FF/256, 1, NE) ----------------
__global__ void k_act(){
    int e = blockIdx.z;
    int idx = blockIdx.x*blockDim.x + threadIdx.x;
    int i = idx >> 12, f = idx & 4095;
    if (i >= g_cnt[e]) return;
    size_t row = (size_t)(e*TT + i);
    float a = g_h1[row*2*FF + f];
    float g = g_h1[row*2*FF + FF + f];
    g_hh[row*FF + f] = a * sigmoidf_(a) * g;
}

// ---------------- K10: deterministic per-token scatter over experts ----------------
__global__ __launch_bounds__(256) void k_scatter(float* __restrict__ out,
                                                 const float* __restrict__ elb){
    int t = blockIdx.x, tid = threadIdx.x;
    float4 ov = ((float4*)(out + (size_t)t*DM))[tid];
    #pragma unroll
    for (int e = 0; e < NE; e++){
        float w = g_wfull[t*4 + e];
        if (w > 0.f){
            int i = g_pos[e*TT + t];
            float4 eo = ((const float4*)(g_eo + (size_t)(e*TT + i)*DM))[tid];
            float4 bv = ((const float4*)(elb + (size_t)e*DM))[tid];
            ov.x += w * (eo.x + bv.x);
            ov.y += w * (eo.y + bv.y);
            ov.z += w * (eo.z + bv.z);
            ov.w += w * (eo.w + bv.w);
        }
    }
    ((float4*)(out + (size_t)t*DM))[tid] = ov;
}

// ---------------- host ----------------
extern "C" void kernel_launch(void* const* d_in, const int* in_sizes, int n_in,
                              void* d_out, int out_size) {
    const float* x      = (const float*)d_in[0];
    const float* goal   = (const float*)d_in[1];
    const float* mem    = (const float*)d_in[2];
    const float* n1w    = (const float*)d_in[3];
    const float* n2w    = (const float*)d_in[4];
    const float* rw     = (const float*)d_in[5];
    const float* xw     = (const float*)d_in[6];
    const float* Amat   = (const float*)d_in[7];
    const float* Dp     = (const float*)d_in[8];
    const float* gate_w = (const float*)d_in[9];
    const float* gate_b = (const float*)d_in[10];
    const float* ssd_o  = (const float*)d_in[11];
    const float* q_w    = (const float*)d_in[12];
    const float* k_w    = (const float*)d_in[13];
    const float* v_w    = (const float*)d_in[14];
    const float* o_w    = (const float*)d_in[15];
    const float* qn     = (const float*)d_in[16];
    const float* kn     = (const float*)d_in[17];
    const float* dw_w   = (const float*)d_in[18];
    const float* dw_b   = (const float*)d_in[19];
    const float* pw_w   = (const float*)d_in[20];
    const float* pw_b   = (const float*)d_in[21];
    const float* mg     = (const float*)d_in[22];
    const float* ew1    = (const float*)d_in[23];
    const float* ew2    = (const float*)d_in[24];
    const float* elw    = (const float*)d_in[25];
    const float* elb    = (const float*)d_in[26];
    float* out = (float*)d_out;

    float *p_xn, *p_gz, *p_yg, *p_ssd, *p_q, *p_k, *p_v, *p_attn, *p_oattn,
          *p_dws, *p_conv, *p_xg, *p_h1, *p_hh, *p_h2, *p_eo;
    cudaGetSymbolAddress((void**)&p_xn,   g_xn);
    cudaGetSymbolAddress((void**)&p_gz,   g_gz);
    cudaGetSymbolAddress((void**)&p_yg,   g_yg);
    cudaGetSymbolAddress((void**)&p_ssd,  g_ssd);
    cudaGetSymbolAddress((void**)&p_q,    g_q);
    cudaGetSymbolAddress((void**)&p_k,    g_k);
    cudaGetSymbolAddress((void**)&p_v,    g_v);
    cudaGetSymbolAddress((void**)&p_attn, g_attn);
    cudaGetSymbolAddress((void**)&p_oattn,g_oattn);
    cudaGetSymbolAddress((void**)&p_dws,  g_dws);
    cudaGetSymbolAddress((void**)&p_conv, g_conv);
    cudaGetSymbolAddress((void**)&p_xg,   g_xg);
    cudaGetSymbolAddress((void**)&p_h1,   g_h1);
    cudaGetSymbolAddress((void**)&p_hh,   g_hh);
    cudaGetSymbolAddress((void**)&p_h2,   g_h2);
    cudaGetSymbolAddress((void**)&p_eo,   g_eo);

    // 1. pre: xn, router weights, ssm projection; conv (xn-only dep)
    k_pre<<<TT, 256>>>(x, goal, n1w, rw, xw);
    k_conv<<<TT*DM/256, 256>>>(dw_w, dw_b);
    // 2. fused SSM scan + C contraction
    k_scan<<<NHH*2, 32>>>(Amat);
    // 3. batched xn-projections on tensor cores (tf32-split, fp32-grade accuracy)
    {
        GArgs ga;
        ga.A[0]=p_xn;  ga.B[0]=gate_w; ga.C[0]=p_gz;   ga.N[0]=DM;
        ga.A[1]=p_xn;  ga.B[1]=q_w;    ga.C[1]=p_q;    ga.N[1]=DM;
        ga.A[2]=p_xn;  ga.B[2]=k_w;    ga.C[2]=p_k;    ga.N[2]=NKV*HD;
        ga.A[3]=p_xn;  ga.B[3]=v_w;    ga.C[3]=p_v;    ga.N[3]=NKV*HD;
        ga.A[4]=p_dws; ga.B[4]=pw_w;   ga.C[4]=p_conv; ga.N[4]=DM;
        gemm_split_multi<<<dim3(DM/128, TT/128, 5), 256>>>(ga, DM);
    }
    k_yg<<<TT, 256>>>(gate_b, Dp);
    k_rope<<<TT*NHH/4, 128>>>(p_q, qn, NHH);
    k_rope<<<TT*NKV/4, 128>>>(p_k, kn, NKV);
    k_attn<<<dim3(LSEQ/64, NHH, 2), 256>>>();
    // 4. batched mid-chain GEMMs: ssd_o (from yg), o (from attn)
    {
        GArgs gb;
        gb.A[0]=p_yg;   gb.B[0]=ssd_o; gb.C[0]=p_ssd;   gb.N[0]=DM;
        gb.A[1]=p_attn; gb.B[1]=o_w;   gb.C[1]=p_oattn; gb.N[1]=DM;
        gb.A[2]=p_xn;   gb.B[2]=ssd_o; gb.C[2]=p_ssd;   gb.N[2]=0;  // unused
        gb.A[3]=p_xn;   gb.B[3]=ssd_o; gb.C[3]=p_ssd;   gb.N[3]=0;
        gb.A[4]=p_xn;   gb.B[4]=ssd_o; gb.C[4]=p_ssd;   gb.N[4]=0;
        gemm_split_multi<<<dim3(DM/128, TT/128, 2), 256>>>(gb, DM);
    }
    // 5. mix -> x2 (seeds out)
    k_mix<<<TT*DM/256, 256>>>(x, mem, pw_b, out);
    // 6. MoE gating + token lists
    k_reset<<<1, 32>>>();
    k_moegate<<<TT, 256>>>(n2w, mg);
    // 7. MoE: all experts batched per stage (top-2 sparse, tf32)
    k_gather<<<dim3(TT, NE), 256>>>();
    gemm_tf32<<<dim3(2*FF/128, TT/128, NE), 256>>>(p_xg, ew1, p_h1, 2*FF, DM,
        (size_t)TT*DM, (size_t)DM*2*FF, (size_t)TT*2*FF);
    k_act<<<dim3(TT*FF/256, 1, NE), 256>>>();
    gemm_tf32<<<dim3(DM/128, TT/128, NE), 256>>>(p_hh, ew2, p_h2, DM, FF,
        (size_t)TT*FF, (size_t)FF*DM, (size_t)TT*DM);
    gemm_tf32<<<dim3(DM/128, TT/128, NE), 256>>>(p_h2, elw, p_eo, DM, DM,
        (size_t)TT*DM, (size_t)DM*DM, (size_t)TT*DM);
    k_scatter<<<TT, 256>>>(out, elb);
}